// round 17
// baseline (speedup 1.0000x reference)
#include <cuda_runtime.h>
#include <cuda_bf16.h>
#include <cuda_fp16.h>
#include <cstdint>
#include <vector>
#include <algorithm>

// ---------------- problem constants ----------------
#define B_    8
#define S_    4096
#define D_    512
#define QT    128
#define NTH   128        // 4 warps, 32 q-rows each
#define NDEP  8

// smem byte offsets (dynamic smem base AB)
// phase A buffers: Q tile 128x128B (16384) + K tile 144x128B (18432) = 34816 per buffer
#define ABUF     34816
#define KOFF     16384
// phase B: V tiles [128 j][40 fp16] pitch 80B (32-d chunks), double buffered (overlays A)
#define VPITCH   80
#define VBUF     10240
#define DYN_BYTES 69632

// ---------------- fp16 scratch (device globals; tile-ready layouts) ----------------
// Q: [b][qblock][ck][row 0..127][64 halves]  (XOR-swizzled rows, 128B each)
__device__ __align__(16) __half g_Qs[B_][32][8][128][64];
// K: [b][ck][row 0..128][64 halves] (swizzled; row128 identity)
__device__ __align__(16) __half g_Ks[B_][8][129][64];
// V: [b][dc][row 0..127][64 halves] (plain d-order)
__device__ __align__(16) __half g_Vs[B_][8][128][64];

// ---------------- host-side Cantor table (keys sorted by (dmin, idx)) ----------------
struct CTab { int idx[129]; };
static CTab g_tab;

static bool build_tables() {
    std::vector<std::vector<long long>> idxd;
    auto to_idx = [](const std::vector<double>& p) {
        std::vector<long long> v;
        for (double x : p) v.push_back((long long)(x * 4095.0));
        std::sort(v.begin(), v.end());
        v.erase(std::unique(v.begin(), v.end()), v.end());
        return v;
    };
    std::vector<double> prev = {0.0, 1.0};
    idxd.push_back(to_idx(prev));
    for (int d = 1; d < NDEP; ++d) {
        std::vector<double> nw;
        for (size_t i = 0; i + 1 < prev.size(); ++i) {
            double left = prev[i], right = prev[i + 1];
            double third = (right - left) / 3.0;
            nw.push_back(left);
            nw.push_back(left + third);
        }
        nw.push_back(prev.back());
        prev.swap(nw);
        idxd.push_back(to_idx(prev));
    }
    const std::vector<long long>& uni = idxd[NDEP - 1];   // 129 keys (nested union)
    int nu = (int)uni.size();
    std::vector<std::pair<int, long long>> keys;
    for (int j = 0; j < nu; ++j) {
        int dm = NDEP - 1;
        for (int d = 0; d < NDEP; ++d)
            if (std::binary_search(idxd[d].begin(), idxd[d].end(), uni[j])) { dm = d; break; }
        keys.push_back({dm, uni[j]});
    }
    std::sort(keys.begin(), keys.end());
    for (int j = 0; j < nu && j < 129; ++j) g_tab.idx[j] = (int)keys[j].second;
    return true;
}
static bool g_built = build_tables();
// sorted-slot depth groups: bnd = {0,2,3,5,9,17,33,65,129}

// ---------------- helpers ----------------
__device__ __forceinline__ uint32_t s2u(const void* p) {
    uint32_t a;
    asm("{ .reg .u64 t; cvta.to.shared.u64 t, %1; cvt.u32.u64 %0, t; }" : "=r"(a) : "l"(p));
    return a;
}

#define LDSM4(r0, r1, r2, r3, addr) \
    asm volatile("ldmatrix.sync.aligned.m8n8.x4.shared.b16 {%0,%1,%2,%3}, [%4];" \
                 : "=r"(r0), "=r"(r1), "=r"(r2), "=r"(r3) : "r"(addr))

#define LDSM4T(r0, r1, r2, r3, addr) \
    asm volatile("ldmatrix.sync.aligned.m8n8.x4.trans.shared.b16 {%0,%1,%2,%3}, [%4];" \
                 : "=r"(r0), "=r"(r1), "=r"(r2), "=r"(r3) : "r"(addr))

#define MMAH(d, a0, a1, a2, a3, b0, b1) \
    asm volatile("mma.sync.aligned.m16n8k16.row.col.f32.f16.f16.f32 " \
                 "{%0,%1,%2,%3}, {%4,%5,%6,%7}, {%8,%9}, {%0,%1,%2,%3};" \
                 : "+f"((d)[0]), "+f"((d)[1]), "+f"((d)[2]), "+f"((d)[3]) \
                 : "r"(a0), "r"(a1), "r"(a2), "r"(a3), "r"(b0), "r"(b1))

#define CP16(dst, src) \
    asm volatile("cp.async.cg.shared.global [%0], [%1], 16;" :: "r"(dst), "l"(src) : "memory")
#define CPCOMMIT() asm volatile("cp.async.commit_group;" ::: "memory")
#define CPWAIT0()  asm volatile("cp.async.wait_group 0;" ::: "memory")

// fp16 split: hi = rn-f16(x), lo = rn-f16(x - hi); pack 2 lanes
__device__ __forceinline__ void split2h(float c0, float c1, uint32_t& hi, uint32_t& lo) {
    __half2 h = __floats2half2_rn(c0, c1);
    hi = *(uint32_t*)&h;
    float2 hf = __half22float2(h);
    __half2 l = __floats2half2_rn(c0 - hf.x, c1 - hf.y);
    lo = *(uint32_t*)&l;
}
__device__ __forceinline__ uint32_t pack_h2(float c0, float c1) {
    __half2 h = __floats2half2_rn(c0, c1);
    return *(uint32_t*)&h;
}

// depth-group accumulation (nt literal after unroll -> all indices static)
__device__ __forceinline__ void gacc(int nt, float* g, float e0, float e1, int t) {
    if (nt == 0) {
        g[0] += (t == 0) ? (e0 + e1) : 0.f;
        g[1] += (t == 1) ? e0 : 0.f;
        g[2] += (t == 1) ? e1 : ((t == 2) ? e0 : 0.f);
        g[3] += (t == 2) ? e1 : ((t == 3) ? (e0 + e1) : 0.f);
    } else if (nt == 1) {
        g[3] += (t == 0) ? e0 : 0.f;
        g[4] += (t == 0) ? e1 : (e0 + e1);
    } else if (nt == 2) {
        g[4] += (t == 0) ? e0 : 0.f;
        g[5] += (t == 0) ? e1 : (e0 + e1);
    } else if (nt == 3) {
        g[5] += e0 + e1;
    } else if (nt == 4) {
        g[5] += (t == 0) ? e0 : 0.f;
        g[6] += (t == 0) ? e1 : (e0 + e1);
    } else if (nt <= 7) {
        g[6] += e0 + e1;
    } else if (nt == 8) {
        g[6] += (t == 0) ? e0 : 0.f;
        g[7] += (t == 0) ? e1 : (e0 + e1);
    } else {
        g[7] += e0 + e1;
    }
}
__device__ __forceinline__ float2 samul(int nt, const float* sa, int t) {
    float m0, m1;
    if (nt == 0) {
        m0 = (t == 0) ? sa[0] : (t == 1) ? sa[1] : (t == 2) ? sa[2] : sa[3];
        m1 = (t == 0) ? sa[0] : (t == 1) ? sa[2] : sa[3];
    } else if (nt == 1) { m0 = (t == 0) ? sa[3] : sa[4]; m1 = sa[4]; }
    else if (nt == 2)   { m0 = (t == 0) ? sa[4] : sa[5]; m1 = sa[5]; }
    else if (nt == 3)   { m0 = sa[5]; m1 = sa[5]; }
    else if (nt == 4)   { m0 = (t == 0) ? sa[5] : sa[6]; m1 = sa[6]; }
    else if (nt <= 7)   { m0 = sa[6]; m1 = sa[6]; }
    else if (nt == 8)   { m0 = (t == 0) ? sa[6] : sa[7]; m1 = sa[7]; }
    else                { m0 = sa[7]; m1 = sa[7]; }
    return make_float2(m0, m1);
}

// ---------------- prepass 1: Q fp32 -> fp16 swizzled tiles (latency-optimized) ----------------
__global__ __launch_bounds__(256)
void prepQ_kernel(const float* __restrict__ Q)
{
    const int qb = blockIdx.x >> 3;
    const int ck = blockIdx.x & 7;
    const int b  = blockIdx.y;
    const int tid = threadIdx.x;
    const float* src = Q + ((size_t)b * S_ + qb * QT) * D_ + ck * 64;
    char* dstb = (char*)&g_Qs[b][qb][ck][0][0];

    float4 a[4], c[4];
    int r[4], p[4];
    #pragma unroll
    for (int i = 0; i < 4; ++i) {
        const int idx = i * 256 + tid;    // 0..1023
        r[i] = idx >> 3;
        p[i] = idx & 7;
        const int k0 = (p[i] ^ (r[i] & 7)) * 8;
        const float* rp = src + (size_t)r[i] * D_ + k0;
        a[i] = *(const float4*)rp;
        c[i] = *(const float4*)(rp + 4);
    }
    #pragma unroll
    for (int i = 0; i < 4; ++i) {
        uint4 o = make_uint4(pack_h2(a[i].x, a[i].y), pack_h2(a[i].z, a[i].w),
                             pack_h2(c[i].x, c[i].y), pack_h2(c[i].z, c[i].w));
        *(uint4*)(dstb + r[i] * 128 + p[i] * 16) = o;
    }
}

// ---------------- prepass 2: gathered K rows (129) + V rows (128) -> fp16 tiles ----------------
__global__ __launch_bounds__(128)
void prepKV_kernel(const float* __restrict__ K, const float* __restrict__ V, CTab tab)
{
    const int j = blockIdx.x;    // 0..128
    const int b = blockIdx.y;    // 0..7
    const int tid = threadIdx.x; // 0..127
    const int row = tab.idx[j];
    const int k  = tid * 4;
    const int ck = k >> 6, kk = k & 63;
    {
        float4 u = *(const float4*)(K + ((size_t)b * S_ + row) * D_ + k);
        char* dst = (char*)&g_Ks[b][ck][j][0] + (((kk >> 3) ^ (j & 7)) * 16) + (kk & 7) * 2;
        *(uint2*)dst = make_uint2(pack_h2(u.x, u.y), pack_h2(u.z, u.w));
    }
    if (j < 128) {
        float4 u = *(const float4*)(V + ((size_t)b * S_ + row) * D_ + k);
        char* dst = (char*)&g_Vs[b][ck][j][0] + kk * 2;
        *(uint2*)dst = make_uint2(pack_h2(u.x, u.y), pack_h2(u.z, u.w));
    }
}

// ---------------- main kernel ----------------
__global__ __launch_bounds__(NTH, 3)
void ufa16_kernel(const float* __restrict__ V, const float* __restrict__ SW,
                  const float* __restrict__ ST, float* __restrict__ O, CTab tab)
{
    extern __shared__ char AB[];
    const uint32_t ab = s2u(AB);

    __shared__ float wv[NDEP];
    __shared__ float c128s[128];

    const int tid  = threadIdx.x;
    const int w    = tid >> 5;      // 0..3
    const int lane = tid & 31;
    const int b    = blockIdx.y;
    const int qb   = blockIdx.x;
    const int q0   = qb * QT;
    const float inv_scale = 0.04419417382415922f;  // 1/sqrt(512)

    const int lr = lane & 15;
    const int lc = lane >> 4;
    const int t4 = lane & 3;
    const int rq = lane >> 2;

    if (tid == 0) {
        float tmp = ST[0];
        float vvv[NDEP];
        float m = -1e30f;
        #pragma unroll
        for (int d = 0; d < NDEP; ++d) { vvv[d] = SW[d] / tmp; m = fmaxf(m, vvv[d]); }
        float s = 0.f;
        #pragma unroll
        for (int d = 0; d < NDEP; ++d) { vvv[d] = __expf(vvv[d] - m); s += vvv[d]; }
        #pragma unroll
        for (int d = 0; d < NDEP; ++d) wv[d] = vvv[d] / s;
    }
    // zero K pad rows 129..143 in BOTH phase-A buffers (cp.async fills only rows 0..128)
    for (int i = tid; i < 240; i += NTH) {
        const int buf = i / 120, rem = i % 120;
        const int row = 129 + rem / 8, ch = rem % 8;
        *(uint4*)(AB + buf * ABUF + KOFF + row * 128 + ch * 16) = make_uint4(0, 0, 0, 0);
    }

    const int si128 = tab.idx[128];

    // ---- cp.async fills ----
    auto fillA = [&](int ck, int s) {
        const uint32_t qdst = ab + s * ABUF;
        const char* qsrc = (const char*)&g_Qs[b][qb][ck][0][0];
        #pragma unroll
        for (int i = 0; i < 8; ++i) {
            const int c = i * 128 + tid;
            CP16(qdst + c * 16, qsrc + c * 16);
        }
        const uint32_t kdst = qdst + KOFF;
        const char* ksrc = (const char*)&g_Ks[b][ck][0][0];
        #pragma unroll
        for (int i = 0; i < 9; ++i) {
            const int c = i * 128 + tid;
            if (c < 1032) CP16(kdst + c * 16, ksrc + c * 16);   // 129 rows x 8 chunks
        }
    };
    // fill V 32-d chunk t into buffer s (rows 0..127, 4x16B per row)
    auto fillV = [&](int t, int s) {
        const uint32_t vdst = ab + s * VBUF;
        const char* vsrc = (const char*)&g_Vs[b][t >> 1][0][0] + (t & 1) * 64;
        #pragma unroll
        for (int i = 0; i < 4; ++i) {
            const int c = i * 128 + tid;        // 0..511 = 128 rows x 4 chunks
            const int j = c >> 2, cc = c & 3;
            CP16(vdst + j * VPITCH + cc * 16, vsrc + j * 128 + cc * 16);
        }
    };

    // ================= phase A: S = Q.K^T (raw), single-fp16 mma, double-buffered =================
    float acc[2][16][4];
    float acc16[2][4];   // score cols 128..135 (only j=128 real)
    #pragma unroll
    for (int mt = 0; mt < 2; ++mt) {
        #pragma unroll
        for (int nt = 0; nt < 16; ++nt)
            #pragma unroll
            for (int i = 0; i < 4; ++i)
                acc[mt][nt][i] = 0.f;
        #pragma unroll
        for (int i = 0; i < 4; ++i) acc16[mt][i] = 0.f;
    }

    fillA(0, 0);
    CPCOMMIT();
    CPWAIT0();
    __syncthreads();

    #pragma unroll 1
    for (int ck = 0; ck < 8; ++ck) {
        const int s = ck & 1;
        if (ck < 7) { fillA(ck + 1, s ^ 1); CPCOMMIT(); }

        const uint32_t qab = ab + s * ABUF;
        const uint32_t kab = qab + KOFF;
        #pragma unroll
        for (int kk = 0; kk < 4; ++kk) {
            const uint32_t coff = (uint32_t)(((2 * kk + lc) ^ (lr & 7)) * 16);
            uint32_t ah[2][4];
            #pragma unroll
            for (int mt = 0; mt < 2; ++mt) {
                const uint32_t arow = (uint32_t)((w * 32 + mt * 16 + lr) * 128);
                LDSM4(ah[mt][0], ah[mt][1], ah[mt][2], ah[mt][3], qab + arow + coff);
            }
            #pragma unroll
            for (int np = 0; np < 8; ++np) {
                const uint32_t boff = (uint32_t)((np * 16 + lr) * 128) + coff;
                uint32_t bh0, bh1, bh2, bh3;
                LDSM4(bh0, bh1, bh2, bh3, kab + boff);
                #pragma unroll
                for (int mt = 0; mt < 2; ++mt) {
                    MMAH(acc[mt][2 * np],     ah[mt][0], ah[mt][1], ah[mt][2], ah[mt][3], bh0, bh2);
                    MMAH(acc[mt][2 * np + 1], ah[mt][0], ah[mt][1], ah[mt][2], ah[mt][3], bh1, bh3);
                }
            }
            // extra n8 tile: score cols 128..135 (rows 128..143 of K tile; 129..143 zero)
            {
                const uint32_t boff = (uint32_t)((128 + lr) * 128) + coff;
                uint32_t bh0, bh1, bh2, bh3;
                LDSM4(bh0, bh1, bh2, bh3, kab + boff);
                #pragma unroll
                for (int mt = 0; mt < 2; ++mt)
                    MMAH(acc16[mt], ah[mt][0], ah[mt][1], ah[mt][2], ah[mt][3], bh0, bh2);
            }
        }
        CPWAIT0();
        __syncthreads();
    }

    // V chunk-0 fill overlaps softmax (phase-A buffers partly overwritten: safe, all dead)
    fillV(0, 0);
    CPCOMMIT();

    // ================= softmax in registers -> C fragments (fp16 hi/lo), per mt =================
    uint32_t chi[2][8][4], clo[2][8][4];
    #pragma unroll
    for (int mt = 0; mt < 2; ++mt) {
        const int qa = w * 32 + mt * 16 + rq;
        const float s128A = __shfl_sync(0xffffffffu, acc16[mt][0], lane & ~3);
        const float s128B = __shfl_sync(0xffffffffu, acc16[mt][2], lane & ~3);

        float mA = s128A, mB = s128B;
        #pragma unroll
        for (int nt = 0; nt < 16; ++nt) {
            mA = fmaxf(mA, fmaxf(acc[mt][nt][0], acc[mt][nt][1]));
            mB = fmaxf(mB, fmaxf(acc[mt][nt][2], acc[mt][nt][3]));
        }
        mA = fmaxf(mA, __shfl_xor_sync(0xffffffffu, mA, 1));
        mA = fmaxf(mA, __shfl_xor_sync(0xffffffffu, mA, 2));
        mB = fmaxf(mB, __shfl_xor_sync(0xffffffffu, mB, 1));
        mB = fmaxf(mB, __shfl_xor_sync(0xffffffffu, mB, 2));

        float gA[NDEP], gB[NDEP];
        #pragma unroll
        for (int d = 0; d < NDEP; ++d) { gA[d] = 0.f; gB[d] = 0.f; }
        #pragma unroll
        for (int nt = 0; nt < 16; ++nt) {
            float e0 = __expf((acc[mt][nt][0] - mA) * inv_scale);
            float e1 = __expf((acc[mt][nt][1] - mA) * inv_scale);
            float e2 = __expf((acc[mt][nt][2] - mB) * inv_scale);
            float e3 = __expf((acc[mt][nt][3] - mB) * inv_scale);
            acc[mt][nt][0] = e0; acc[mt][nt][1] = e1;
            acc[mt][nt][2] = e2; acc[mt][nt][3] = e3;
            gacc(nt, gA, e0, e1, t4);
            gacc(nt, gB, e2, e3, t4);
        }
        // quad reduction FIRST...
        #pragma unroll
        for (int d = 0; d < NDEP; ++d) {
            gA[d] += __shfl_xor_sync(0xffffffffu, gA[d], 1);
            gA[d] += __shfl_xor_sync(0xffffffffu, gA[d], 2);
            gB[d] += __shfl_xor_sync(0xffffffffu, gB[d], 1);
            gB[d] += __shfl_xor_sync(0xffffffffu, gB[d], 2);
        }
        // ...THEN the (quad-uniform) j=128 term, added exactly once
        const float eA128 = __expf((s128A - mA) * inv_scale);
        const float eB128 = __expf((s128B - mB) * inv_scale);
        gA[7] += eA128;
        gB[7] += eB128;

        float ZA = 0.f, ZB = 0.f, saA[NDEP], saB[NDEP];
        #pragma unroll
        for (int d = 0; d < NDEP; ++d) {
            ZA += gA[d]; saA[d] = __fdividef(wv[d], ZA);
            ZB += gB[d]; saB[d] = __fdividef(wv[d], ZB);
        }
        float sA = 0.f, sB = 0.f;
        #pragma unroll
        for (int d = NDEP - 1; d >= 0; --d) {
            sA += saA[d]; saA[d] = sA;
            sB += saB[d]; saB[d] = sB;
        }
        if (t4 == 0) {
            c128s[qa]     = eA128 * saA[7];
            c128s[qa + 8] = eB128 * saB[7];
        }
        #pragma unroll
        for (int nt = 0; nt < 16; ++nt) {
            float2 muA = samul(nt, saA, t4);
            float2 muB = samul(nt, saB, t4);
            const int kk = nt >> 1;
            const int o  = (nt & 1) * 2;
            split2h(acc[mt][nt][0] * muA.x, acc[mt][nt][1] * muA.y, chi[mt][kk][o],     clo[mt][kk][o]);
            split2h(acc[mt][nt][2] * muB.x, acc[mt][nt][3] * muB.y, chi[mt][kk][o + 1], clo[mt][kk][o + 1]);
        }
    }

    CPWAIT0();
    __syncthreads();

    // ================= phase B: O = C . V  (16 d-chunks of 32, double-buffered fp16 V) =================
    #pragma unroll 1
    for (int t = 0; t < 16; ++t) {
        const int s = t & 1;
        if (t < 15) { fillV(t + 1, s ^ 1); CPCOMMIT(); }

        float oa[2][4][4];
        #pragma unroll
        for (int mt = 0; mt < 2; ++mt)
            #pragma unroll
            for (int nt = 0; nt < 4; ++nt)
                #pragma unroll
                for (int i = 0; i < 4; ++i)
                    oa[mt][nt][i] = 0.f;

        const uint32_t vbase = ab + s * VBUF + (lane & 15) * VPITCH + (lane >> 4) * 16;
        #pragma unroll
        for (int kk = 0; kk < 8; ++kk) {
            #pragma unroll
            for (int ng = 0; ng < 2; ++ng) {
                const uint32_t a0 = vbase + kk * (16 * VPITCH) + ng * 32;
                uint32_t vh0, vh1, vh2, vh3;
                LDSM4T(vh0, vh1, vh2, vh3, a0);
                #pragma unroll
                for (int mt = 0; mt < 2; ++mt) {
                    MMAH(oa[mt][2 * ng],     chi[mt][kk][0], chi[mt][kk][1], chi[mt][kk][2], chi[mt][kk][3], vh0, vh1);
                    MMAH(oa[mt][2 * ng],     clo[mt][kk][0], clo[mt][kk][1], clo[mt][kk][2], clo[mt][kk][3], vh0, vh1);
                    MMAH(oa[mt][2 * ng + 1], chi[mt][kk][0], chi[mt][kk][1], chi[mt][kk][2], chi[mt][kk][3], vh2, vh3);
                    MMAH(oa[mt][2 * ng + 1], clo[mt][kk][0], clo[mt][kk][1], clo[mt][kk][2], clo[mt][kk][3], vh2, vh3);
                }
            }
        }

        // epilogue: add key-128 term (fp32), store O
        {
            const float* v128 = V + ((size_t)b * S_ + si128) * D_ + t * 32;
            #pragma unroll
            for (int mt = 0; mt < 2; ++mt) {
                const int qa = w * 32 + mt * 16 + rq;
                const float cA = c128s[qa], cB = c128s[qa + 8];
                float* OA = O + ((size_t)b * S_ + q0 + qa) * D_ + t * 32;
                float* OB = OA + 8 * D_;
                #pragma unroll
                for (int nt = 0; nt < 4; ++nt) {
                    const int nc = nt * 8 + 2 * t4;
                    const float2 vv = *(const float2*)(v128 + nc);
                    *(float2*)(OA + nc) = make_float2(oa[mt][nt][0] + cA * vv.x, oa[mt][nt][1] + cA * vv.y);
                    *(float2*)(OB + nc) = make_float2(oa[mt][nt][2] + cB * vv.x, oa[mt][nt][3] + cB * vv.y);
                }
            }
        }
        CPWAIT0();
        __syncthreads();
    }
}

// ---------------- launch ----------------
extern "C" void kernel_launch(void* const* d_in, const int* in_sizes, int n_in,
                              void* d_out, int out_size)
{
    const float* Q  = (const float*)d_in[0];
    const float* K  = (const float*)d_in[1];
    const float* V  = (const float*)d_in[2];
    // d_in[3] = t (unused by the reference)
    const float* SW = (const float*)d_in[4];
    const float* ST = (const float*)d_in[5];
    float* O = (float*)d_out;

    // prepass: fp16 conversions into tile-ready scratch
    prepQ_kernel<<<dim3(256, B_), 256>>>(Q);
    prepKV_kernel<<<dim3(129, B_), 128>>>(K, V, g_tab);

    cudaFuncSetAttribute(ufa16_kernel, cudaFuncAttributeMaxDynamicSharedMemorySize, DYN_BYTES);
    dim3 grid(S_ / QT, B_);
    ufa16_kernel<<<grid, NTH, DYN_BYTES>>>(V, SW, ST, O, g_tab);
}